// round 5
// baseline (speedup 1.0000x reference)
#include <cuda_runtime.h>
#include <cuda_bf16.h>

#define NUM_BINS 32
#define NBINS2   (NUM_BINS * NUM_BINS)
#define EPS 1e-5f

// Zero-initialized device globals (no allocations allowed).
// Invariant: at kernel entry g_hist == 0 and g_done == 0; the last CTA
// restores this invariant before exiting, so every graph replay sees the
// same initial state (deterministic).
__device__ unsigned int g_hist[NBINS2];
__device__ unsigned int g_done;

__device__ __forceinline__ int bin_of(float v) {
    // matches jnp.round(v / 255.0 * 31): IEEE div, mul, round-half-even
    return (int)rintf((v / 255.0f) * 31.0f);
}

__device__ __forceinline__ void accum4(unsigned int* sh, float4 a, float4 b) {
    atomicAdd(&sh[bin_of(a.x) * NUM_BINS + bin_of(b.x)], 1u);
    atomicAdd(&sh[bin_of(a.y) * NUM_BINS + bin_of(b.y)], 1u);
    atomicAdd(&sh[bin_of(a.z) * NUM_BINS + bin_of(b.z)], 1u);
    atomicAdd(&sh[bin_of(a.w) * NUM_BINS + bin_of(b.w)], 1u);
}

__global__ void __launch_bounds__(512) lmi_fused_kernel(
    const float4* __restrict__ I4,
    const float4* __restrict__ J4,
    int n4,
    float inv_total,
    float* __restrict__ out)
{
    __shared__ unsigned int sh[NBINS2];
    const int t = threadIdx.x;

    for (int i = t; i < NBINS2; i += blockDim.x) sh[i] = 0u;
    __syncthreads();

    // ---- Phase 1: histogram (2x unrolled grid-stride, 4 outstanding LDG.128) ----
    const int stride = gridDim.x * blockDim.x;
    int i = blockIdx.x * blockDim.x + t;
    for (; i + stride < n4; i += 2 * stride) {
        float4 a0 = I4[i];
        float4 b0 = J4[i];
        float4 a1 = I4[i + stride];
        float4 b1 = J4[i + stride];
        accum4(sh, a0, b0);
        accum4(sh, a1, b1);
    }
    if (i < n4) {
        float4 a0 = I4[i];
        float4 b0 = J4[i];
        accum4(sh, a0, b0);
    }
    __syncthreads();

    // ---- Phase 2: flush block histogram to global ----
    for (int k = t; k < NBINS2; k += blockDim.x) {
        unsigned int v = sh[k];
        if (v) atomicAdd(&g_hist[k], v);
    }

    // ---- Phase 3: last CTA computes MI and resets state ----
    __shared__ bool is_last;
    __threadfence();  // order flush atomics before the counter
    if (t == 0) {
        unsigned int done = atomicAdd(&g_done, 1u);
        is_last = (done == gridDim.x - 1);
    }
    __syncthreads();
    if (!is_last) return;

    __shared__ float jp[NBINS2];
    __shared__ float rowp[NUM_BINS];
    __shared__ float colp[NUM_BINS];
    __shared__ float warp_sums[16];

    // read with .cg to bypass L1 (atomics landed in L2), then reset for next replay
    jp[t]       = (float)__ldcg(&g_hist[t])       * inv_total;
    jp[t + 512] = (float)__ldcg(&g_hist[t + 512]) * inv_total;
    __syncthreads();
    g_hist[t] = 0u;
    g_hist[t + 512] = 0u;
    if (t == 0) g_done = 0u;

    if (t < NUM_BINS) {
        float s = 0.0f;
        #pragma unroll
        for (int c = 0; c < NUM_BINS; c++) s += jp[t * NUM_BINS + c];
        rowp[t] = s;
    } else if (t < 2 * NUM_BINS) {
        int c = t - NUM_BINS;
        float s = 0.0f;
        #pragma unroll
        for (int r = 0; r < NUM_BINS; r++) s += jp[r * NUM_BINS + c];
        colp[c] = s;
    }
    __syncthreads();

    float term = 0.0f;
    #pragma unroll
    for (int u = 0; u < 2; u++) {
        int b = t + u * 512;
        float p  = jp[b];
        float pi = rowp[b >> 5];
        float pj = colp[b & 31];
        term += p * (logf(p + EPS) - logf(pi + EPS) - logf(pj + EPS));
    }

    #pragma unroll
    for (int off = 16; off > 0; off >>= 1)
        term += __shfl_xor_sync(0xFFFFFFFFu, term, off);
    if ((t & 31) == 0) warp_sums[t >> 5] = term;
    __syncthreads();
    if (t < 16) {
        float s = warp_sums[t];
        #pragma unroll
        for (int off = 8; off > 0; off >>= 1)
            s += __shfl_xor_sync(0xFFFFu, s, off);
        if (t == 0) {
            // sigmoid(-mi) = 1 / (1 + exp(mi))
            out[0] = 1.0f / (1.0f + expf(s));
        }
    }
}

extern "C" void kernel_launch(void* const* d_in, const int* in_sizes, int n_in,
                              void* d_out, int out_size)
{
    const float* I = (const float*)d_in[0];
    const float* J = (const float*)d_in[1];
    float* out = (float*)d_out;
    const int n  = in_sizes[0];   // 33,554,432
    const int n4 = n / 4;

    const int threads = 512;
    const int blocks  = 148 * 4;  // 592 CTAs, 4/SM
    lmi_fused_kernel<<<blocks, threads>>>((const float4*)I, (const float4*)J,
                                          n4, 1.0f / (float)n, out);
}